// round 11
// baseline (speedup 1.0000x reference)
#include <cuda_runtime.h>
#include <cuda_fp16.h>
#include <cstdint>
#include <cstddef>

#define THREADS 512
#define M_TILE  64
#define NTILES  1024          // 65536 / 64
#define GRID    148
#define STEPS   12
#define KD      128
#define KK_STEPS 8

// ---- smem layout (bytes from dynamic base) ----
#define OFF_W    0            // 512 rows * 256B fp16 swizzled   = 131072
#define OFF_W2   131072       // 512 rows * 48B  [wx,wy,bz,0..]  =  24576
#define OFF_WHPB 155648       // 8 rows * 256B   [whp_x; whp_y]  =   2048
#define OFF_X    157696       // 2 x (64 rows * 256B) ping-pong  =  32768
#define XBUF_BYTES 16384
#define SMEM_BYTES 190464

#define C_ONE0 0x00003C00u    // fp16x2 (1.0, 0.0)

__device__ __forceinline__ uint32_t smem_u32(const void* p) {
    uint32_t a;
    asm("{ .reg .u64 t; cvta.to.shared.u64 t, %1; cvt.u32.u64 %0, t; }" : "=r"(a) : "l"(p));
    return a;
}
__device__ __forceinline__ uint32_t packh2(float lo, float hi) {
    uint32_t r; asm("cvt.rn.f16x2.f32 %0, %1, %2;" : "=r"(r) : "f"(hi), "f"(lo)); return r;
}
__device__ __forceinline__ float tanh_ap(float x) {
    float y; asm("tanh.approx.f32 %0, %1;" : "=f"(y) : "f"(x)); return y;
}
__device__ __forceinline__ float siga(float x) { return fmaf(tanh_ap(0.5f * x), 0.5f, 0.5f); }

#define LDSM_X4(r0, r1, r2, r3, addr)                                                  \
    asm volatile("ldmatrix.sync.aligned.m8n8.x4.shared.b16 {%0,%1,%2,%3}, [%4];"       \
                 : "=r"(r0), "=r"(r1), "=r"(r2), "=r"(r3) : "r"(addr))

#define MMA16816(d, a0, a1, a2, a3, b0, b1)                                            \
    asm volatile("mma.sync.aligned.m16n8k16.row.col.f32.f16.f16.f32 "                  \
                 "{%0,%1,%2,%3}, {%4,%5,%6,%7}, {%8,%9}, {%0,%1,%2,%3};"               \
                 : "+f"((d)[0]), "+f"((d)[1]), "+f"((d)[2]), "+f"((d)[3])              \
                 : "r"(a0), "r"(a1), "r"(a2), "r"(a3), "r"(b0), "r"(b1))

// swizzled byte offset within a 256B-row fp16 tile
__device__ __forceinline__ uint32_t swz_off(int r, int k) {
    return (uint32_t)(r * 256 + ((((k >> 3) ^ (r & 7)) << 4) | ((k & 7) * 2)));
}

__global__ __launch_bounds__(THREADS, 1)
void decoder_mma(const float* __restrict__ lpr, const float* __restrict__ h0,
                 const float* __restrict__ c0,
                 const float* __restrict__ w_ih, const float* __restrict__ w_hh,
                 const float* __restrict__ b_ih, const float* __restrict__ b_hh,
                 const float* __restrict__ w_se, const float* __restrict__ b_se,
                 const float* __restrict__ w_hp, const float* __restrict__ b_hp,
                 float2* __restrict__ out)
{
    extern __shared__ char S[];
    const uint32_t Sb = smem_u32(S);

    const int tid = threadIdx.x, lane = tid & 31, w = tid >> 5;
    const int mg = w & 1, ng = w >> 1;        // 2 M-groups x 8 N-groups, warp m32n64
    const int g4 = lane >> 2, c2 = (lane & 3) * 2;
    const bool is_c0 = (lane & 3) == 0;

    const float bhx = __ldg(b_hp), bhy = __ldg(b_hp + 1);

    // ================= one-time prep =================
    // W row reorder: n = ng*64 + gate*16 + ul  ->  global gate row gate*128 + ng*16 + ul
    for (int i = tid; i < 512 * KD; i += THREADS) {
        int n = i >> 7, k = i & 127;
        int grow = ((n >> 4) & 3) * 128 + (n >> 6) * 16 + (n & 15);
        *(__half*)(S + OFF_W + swz_off(n, k)) = __float2half_rn(w_hh[grow * 128 + k]);
    }
    // zero W2 + WHPB (contiguous 26624 B)
    for (int i = tid; i < (24576 + 2048) / 4; i += THREADS)
        ((uint32_t*)(S + OFF_W2))[i] = 0;
    __syncthreads();
    // W2 rows: [wx, wy, bz] fp16 (rank-2 folded dec_in weights + folded bias)
    for (int n = tid; n < 512; n += THREADS) {
        int grow = ((n >> 4) & 3) * 128 + (n >> 6) * 16 + (n & 15);
        float wx = 0.f, wy = 0.f, bz = b_ih[grow] + b_hh[grow];
        for (int e = 0; e < 64; e++) {
            float wv = w_ih[grow * 64 + e];
            wx = fmaf(wv, w_se[e * 2],     wx);
            wy = fmaf(wv, w_se[e * 2 + 1], wy);
            bz = fmaf(wv, b_se[e],         bz);
        }
        __half* w2r = (__half*)(S + OFF_W2 + n * 48);
        w2r[0] = __float2half_rn(wx);
        w2r[1] = __float2half_rn(wy);
        w2r[2] = __float2half_rn(bz);
    }
    // WHPB: row 0 = w_hp_x[k], row 1 = w_hp_y[k], rows 2-7 zero (swizzled like W)
    for (int i = tid; i < 2 * KD; i += THREADS) {
        int n = i >> 7, k = i & 127;
        *(__half*)(S + OFF_WHPB + swz_off(n, k)) = __float2half_rn(w_hp[n * 128 + k]);
    }

    // ldmatrix per-lane address components
    const uint32_t ax_     = (uint32_t)(lane & 7);
    const uint32_t asel    = (uint32_t)(lane >> 4);
    const uint32_t arowoff = (uint32_t)(mg * 32 + (lane & 15)) * 256;
    const uint32_t bdn     = (uint32_t)((lane & 7) + ((lane >> 4) << 3));
    const uint32_t bbase   = Sb + OFF_W + (uint32_t)(ng * 64 + bdn) * 256;
    const uint32_t bk_     = (uint32_t)((lane >> 3) & 1);
    const uint32_t w2base  = Sb + OFF_W2 + (uint32_t)(ng * 64 + bdn) * 48 + (bk_ << 4);
    const uint32_t hpbase  = Sb + OFF_WHPB + (uint32_t)(bdn & 7) * 256;

    // ================= persistent tile loop =================
    for (int tile = blockIdx.x; tile < NTILES; tile += gridDim.x) {
        const int pedb = tile * M_TILE;
        __syncthreads();   // previous tile fully drained (incl. ng0 final pass)

        // ---- init: h0 -> X buffer 0, c0 -> regs ----
        for (int i = tid; i < 64 * 64; i += THREADS) {
            int r = i >> 6, kp = (i & 63) * 2;
            float2 hv = *(const float2*)(h0 + (size_t)(pedb + r) * 128 + kp);
            *(uint32_t*)(S + OFF_X + swz_off(r, kp)) = packh2(hv.x, hv.y);
        }
        float c_arr[16];   // [mt][up8][e][row8]
#pragma unroll
        for (int mt = 0; mt < 2; mt++)
#pragma unroll
            for (int up8 = 0; up8 < 2; up8++)
#pragma unroll
                for (int row8 = 0; row8 < 2; row8++) {
                    int gp = pedb + mg * 32 + mt * 16 + g4 + row8 * 8;
                    int U0 = ng * 16 + up8 * 8 + c2;
                    float2 cv = *(const float2*)(c0 + (size_t)gp * 128 + U0);
                    c_arr[mt * 8 + up8 * 4 + row8]     = cv.x;
                    c_arr[mt * 8 + up8 * 4 + 2 + row8] = cv.y;
                }
        __syncthreads();

        int par = 0;
        // ================= 12 recurrent steps =================
        for (int st = 0; st < STEPS; st++) {
            const uint32_t abase = Sb + OFF_X + (uint32_t)par * XBUF_BYTES + arowoff;
            const uint32_t xw    = (uint32_t)(par ^ 1) * XBUF_BYTES;

            // ---- main GEMM: gates = h @ Whh^T, plus rel cols h @ whp^T ----
            float acc[2][8][4];
            float rac[2][4];
#pragma unroll
            for (int mt = 0; mt < 2; mt++) {
#pragma unroll
                for (int nt = 0; nt < 8; nt++)
#pragma unroll
                    for (int j = 0; j < 4; j++) acc[mt][nt][j] = 0.f;
#pragma unroll
                for (int j = 0; j < 4; j++) rac[mt][j] = 0.f;
            }

#pragma unroll
            for (int kk = 0; kk < KK_STEPS; kk++) {
                const uint32_t koff = (((uint32_t)(2 * kk) + asel) ^ ax_) << 4;
                uint32_t a0[4], a1[4];
                LDSM_X4(a0[0], a0[1], a0[2], a0[3], abase + koff);
                LDSM_X4(a1[0], a1[1], a1[2], a1[3], abase + 4096 + koff);
                const uint32_t bkoff = (((uint32_t)(2 * kk) + bk_) ^ ax_) << 4;
#pragma unroll
                for (int t2 = 0; t2 < 4; t2++) {
                    uint32_t b0, b1, b2, b3;
                    LDSM_X4(b0, b1, b2, b3, bbase + (uint32_t)t2 * 4096 + bkoff);
                    MMA16816(acc[0][2 * t2],     a0[0], a0[1], a0[2], a0[3], b0, b1);
                    MMA16816(acc[0][2 * t2 + 1], a0[0], a0[1], a0[2], a0[3], b2, b3);
                    MMA16816(acc[1][2 * t2],     a1[0], a1[1], a1[2], a1[3], b0, b1);
                    MMA16816(acc[1][2 * t2 + 1], a1[0], a1[1], a1[2], a1[3], b2, b3);
                }
                {   // rel columns (n8): B rows 0..7 of WHPB
                    uint32_t p0, p1, p2, p3;
                    LDSM_X4(p0, p1, p2, p3, hpbase + bkoff);
                    MMA16816(rac[0], a0[0], a0[1], a0[2], a0[3], p0, p1);
                    MMA16816(rac[1], a1[0], a1[1], a1[2], a1[3], p0, p1);
                }
            }

            // ---- build X2 A fragment in registers; emit out[st-1] ----
            uint32_t xa0[2], xa1[2];
#pragma unroll
            for (int mt = 0; mt < 2; mt++) {
                if (is_c0) {
                    float rx0, ry0, rx1, ry1;
                    if (st == 0) {
                        int r0g = pedb + mg * 32 + mt * 16 + g4;
                        float2 v0 = *(const float2*)(lpr + (size_t)r0g * 2);
                        float2 v1 = *(const float2*)(lpr + (size_t)(r0g + 8) * 2);
                        rx0 = v0.x; ry0 = v0.y; rx1 = v1.x; ry1 = v1.y;
                    } else {
                        rx0 = rac[mt][0] + bhx; ry0 = rac[mt][1] + bhy;
                        rx1 = rac[mt][2] + bhx; ry1 = rac[mt][3] + bhy;
                        if (ng == 0) {   // emit out[st-1]
                            int r0g = pedb + mg * 32 + mt * 16 + g4;
                            out[(size_t)(st - 1) * 65536 + r0g]     = make_float2(rx0, ry0);
                            out[(size_t)(st - 1) * 65536 + r0g + 8] = make_float2(rx1, ry1);
                        }
                    }
                    xa0[mt] = packh2(rx0, ry0);
                    xa1[mt] = packh2(rx1, ry1);
                } else if (c2 == 2) {
                    xa0[mt] = C_ONE0; xa1[mt] = C_ONE0;
                } else {
                    xa0[mt] = 0u; xa1[mt] = 0u;
                }
            }

            {   // extra k16 step: rank-2 dec_in + bias ([rx,ry,1] @ W2^T)
#pragma unroll
                for (int t2 = 0; t2 < 4; t2++) {
                    uint32_t b0, b1, b2, b3;
                    LDSM_X4(b0, b1, b2, b3, w2base + (uint32_t)t2 * 768);
                    MMA16816(acc[0][2 * t2],     xa0[0], xa1[0], 0u, 0u, b0, b1);
                    MMA16816(acc[0][2 * t2 + 1], xa0[0], xa1[0], 0u, 0u, b2, b3);
                    MMA16816(acc[1][2 * t2],     xa0[1], xa1[1], 0u, 0u, b0, b1);
                    MMA16816(acc[1][2 * t2 + 1], xa0[1], xa1[1], 0u, 0u, b2, b3);
                }
            }

            // ---- epilogue: pure activations; new h -> other X buf ----
#pragma unroll
            for (int mt = 0; mt < 2; mt++) {
#pragma unroll
                for (int up8 = 0; up8 < 2; up8++) {
                    float hp[2][2];   // [row8][e]
#pragma unroll
                    for (int e = 0; e < 2; e++) {
#pragma unroll
                        for (int row8 = 0; row8 < 2; row8++) {
                            int reg = row8 * 2 + e;
                            float gi = acc[mt][up8][reg];
                            float gf = acc[mt][2 + up8][reg];
                            float gg = acc[mt][4 + up8][reg];
                            float go = acc[mt][6 + up8][reg];
                            int ci = mt * 8 + up8 * 4 + e * 2 + row8;
                            float cc = siga(gf) * c_arr[ci] + siga(gi) * tanh_ap(gg);
                            c_arr[ci] = cc;
                            float h = siga(go) * tanh_ap(cc);
                            hp[row8][e] = h;
                        }
                    }
                    int k0 = ng * 16 + up8 * 8 + c2;
#pragma unroll
                    for (int row8 = 0; row8 < 2; row8++) {
                        int r = mg * 32 + mt * 16 + g4 + row8 * 8;
                        *(uint32_t*)(S + OFF_X + xw + swz_off(r, k0)) =
                            packh2(hp[row8][0], hp[row8][1]);
                    }
                }
            }
            __syncthreads();   // X[par^1] complete, CTA-wide — ONE barrier per step
            par ^= 1;
        }

        // ---- final rel pass: out[11] = h_12 @ whp^T + bhp (ng0 warps only) ----
        if (ng == 0) {
            const uint32_t abase = Sb + OFF_X + (uint32_t)par * XBUF_BYTES + arowoff;
            float rac[2][4];
#pragma unroll
            for (int mt = 0; mt < 2; mt++)
#pragma unroll
                for (int j = 0; j < 4; j++) rac[mt][j] = 0.f;
#pragma unroll
            for (int kk = 0; kk < KK_STEPS; kk++) {
                const uint32_t koff = (((uint32_t)(2 * kk) + asel) ^ ax_) << 4;
                const uint32_t bkoff = (((uint32_t)(2 * kk) + bk_) ^ ax_) << 4;
                uint32_t a0[4], a1[4], p0, p1, p2, p3;
                LDSM_X4(a0[0], a0[1], a0[2], a0[3], abase + koff);
                LDSM_X4(a1[0], a1[1], a1[2], a1[3], abase + 4096 + koff);
                LDSM_X4(p0, p1, p2, p3, hpbase + bkoff);
                MMA16816(rac[0], a0[0], a0[1], a0[2], a0[3], p0, p1);
                MMA16816(rac[1], a1[0], a1[1], a1[2], a1[3], p0, p1);
            }
            if (is_c0) {
#pragma unroll
                for (int mt = 0; mt < 2; mt++) {
                    int r0g = pedb + mg * 32 + mt * 16 + g4;
                    out[(size_t)11 * 65536 + r0g] =
                        make_float2(rac[mt][0] + bhx, rac[mt][1] + bhy);
                    out[(size_t)11 * 65536 + r0g + 8] =
                        make_float2(rac[mt][2] + bhx, rac[mt][3] + bhy);
                }
            }
        }
    }
}

extern "C" void kernel_launch(void* const* d_in, const int* in_sizes, int n_in,
                              void* d_out, int out_size) {
    (void)in_sizes; (void)n_in; (void)out_size;
    const float* lpr  = (const float*)d_in[1];
    const float* h0   = (const float*)d_in[2];
    const float* c0   = (const float*)d_in[3];
    const float* w_ih = (const float*)d_in[4];
    const float* w_hh = (const float*)d_in[5];
    const float* b_ih = (const float*)d_in[6];
    const float* b_hh = (const float*)d_in[7];
    const float* w_se = (const float*)d_in[8];
    const float* b_se = (const float*)d_in[9];
    const float* w_hp = (const float*)d_in[10];
    const float* b_hp = (const float*)d_in[11];

    cudaFuncSetAttribute(decoder_mma, cudaFuncAttributeMaxDynamicSharedMemorySize, SMEM_BYTES);
    decoder_mma<<<GRID, THREADS, SMEM_BYTES>>>(lpr, h0, c0, w_ih, w_hh, b_ih, b_hh,
                                               w_se, b_se, w_hp, b_hp, (float2*)d_out);
}

// round 12
// speedup vs baseline: 1.0469x; 1.0469x over previous
#include <cuda_runtime.h>
#include <cuda_fp16.h>
#include <cstdint>
#include <cstddef>

#define THREADS 512
#define M_TILE  32            // per group
#define NPAIRS  1024          // 65536 / (2*32)
#define GRID    148
#define STEPS   12
#define KD      128
#define KK_STEPS 8

// ---- smem layout (bytes from dynamic base) ----
#define OFF_W    0            // 512 rows * 256B fp16 swizzled   = 131072
#define OFF_W2   131072       // 512 rows * 48B  [wx,wy,bz,0..]  =  24576
#define OFF_WHPB 155648       // 8 rows * 256B   [whp_x; whp_y]  =   2048
#define OFF_X    157696       // 2 grp x 2 buf x (32*256B)       =  32768
#define XBUF_BYTES 8192
#define SMEM_BYTES 190464

#define C_ONE0 0x00003C00u    // fp16x2 (1.0, 0.0)

__device__ __forceinline__ uint32_t smem_u32(const void* p) {
    uint32_t a;
    asm("{ .reg .u64 t; cvta.to.shared.u64 t, %1; cvt.u32.u64 %0, t; }" : "=r"(a) : "l"(p));
    return a;
}
__device__ __forceinline__ uint32_t packh2(float lo, float hi) {
    uint32_t r; asm("cvt.rn.f16x2.f32 %0, %1, %2;" : "=r"(r) : "f"(hi), "f"(lo)); return r;
}
__device__ __forceinline__ float tanh_ap(float x) {
    float y; asm("tanh.approx.f32 %0, %1;" : "=f"(y) : "f"(x)); return y;
}
__device__ __forceinline__ float siga(float x) { return fmaf(tanh_ap(0.5f * x), 0.5f, 0.5f); }

#define BAR_SYNC(id) asm volatile("bar.sync %0, 256;" :: "r"(id) : "memory")

#define LDSM_X4(r0, r1, r2, r3, addr)                                                  \
    asm volatile("ldmatrix.sync.aligned.m8n8.x4.shared.b16 {%0,%1,%2,%3}, [%4];"       \
                 : "=r"(r0), "=r"(r1), "=r"(r2), "=r"(r3) : "r"(addr))

#define MMA16816(d, a0, a1, a2, a3, b0, b1)                                            \
    asm volatile("mma.sync.aligned.m16n8k16.row.col.f32.f16.f16.f32 "                  \
                 "{%0,%1,%2,%3}, {%4,%5,%6,%7}, {%8,%9}, {%0,%1,%2,%3};"               \
                 : "+f"((d)[0]), "+f"((d)[1]), "+f"((d)[2]), "+f"((d)[3])              \
                 : "r"(a0), "r"(a1), "r"(a2), "r"(a3), "r"(b0), "r"(b1))

// swizzled byte offset within a 256B-row fp16 tile
__device__ __forceinline__ uint32_t swz_off(int r, int k) {
    return (uint32_t)(r * 256 + ((((k >> 3) ^ (r & 7)) << 4) | ((k & 7) * 2)));
}

__global__ __launch_bounds__(THREADS, 1)
void decoder_mma(const float* __restrict__ lpr, const float* __restrict__ h0,
                 const float* __restrict__ c0,
                 const float* __restrict__ w_ih, const float* __restrict__ w_hh,
                 const float* __restrict__ b_ih, const float* __restrict__ b_hh,
                 const float* __restrict__ w_se, const float* __restrict__ b_se,
                 const float* __restrict__ w_hp, const float* __restrict__ b_hp,
                 float2* __restrict__ out)
{
    extern __shared__ char S[];
    const uint32_t Sb = smem_u32(S);

    const int tid = threadIdx.x, lane = tid & 31, w = tid >> 5;
    const int grp = w >> 3;                   // two independent 8-warp groups
    const int ng  = w & 7;                    // 8 N-groups; warp m32 x n64
    const int tg  = tid & 255;                // thread id within group
    const int g4 = lane >> 2, c2 = (lane & 3) * 2;
    const bool is_c0 = (lane & 3) == 0;
    const int barid = grp + 1;                // named barrier per group

    const float bhx = __ldg(b_hp), bhy = __ldg(b_hp + 1);

    // ================= one-time prep (full CTA) =================
    for (int i = tid; i < 512 * KD; i += THREADS) {
        int n = i >> 7, k = i & 127;
        int grow = ((n >> 4) & 3) * 128 + (n >> 6) * 16 + (n & 15);
        *(__half*)(S + OFF_W + swz_off(n, k)) = __float2half_rn(w_hh[grow * 128 + k]);
    }
    for (int i = tid; i < (24576 + 2048) / 4; i += THREADS)
        ((uint32_t*)(S + OFF_W2))[i] = 0;
    __syncthreads();
    for (int n = tid; n < 512; n += THREADS) {
        int grow = ((n >> 4) & 3) * 128 + (n >> 6) * 16 + (n & 15);
        float wx = 0.f, wy = 0.f, bz = b_ih[grow] + b_hh[grow];
        for (int e = 0; e < 64; e++) {
            float wv = w_ih[grow * 64 + e];
            wx = fmaf(wv, w_se[e * 2],     wx);
            wy = fmaf(wv, w_se[e * 2 + 1], wy);
            bz = fmaf(wv, b_se[e],         bz);
        }
        __half* w2r = (__half*)(S + OFF_W2 + n * 48);
        w2r[0] = __float2half_rn(wx);
        w2r[1] = __float2half_rn(wy);
        w2r[2] = __float2half_rn(bz);
    }
    for (int i = tid; i < 2 * KD; i += THREADS) {
        int n = i >> 7, k = i & 127;
        *(__half*)(S + OFF_WHPB + swz_off(n, k)) = __float2half_rn(w_hp[n * 128 + k]);
    }
    __syncthreads();   // weights ready for both groups

    // ldmatrix per-lane address components
    const uint32_t ax_     = (uint32_t)(lane & 7);
    const uint32_t asel    = (uint32_t)(lane >> 4);
    const uint32_t arowoff = (uint32_t)(lane & 15) * 256;
    const uint32_t bdn     = (uint32_t)((lane & 7) + ((lane >> 4) << 3));
    const uint32_t bbase   = Sb + OFF_W + (uint32_t)(ng * 64 + bdn) * 256;
    const uint32_t bk_     = (uint32_t)((lane >> 3) & 1);
    const uint32_t w2base  = Sb + OFF_W2 + (uint32_t)(ng * 64 + bdn) * 48 + (bk_ << 4);
    const uint32_t hpbase  = Sb + OFF_WHPB + (uint32_t)(bdn & 7) * 256;
    const uint32_t xgbase  = Sb + OFF_X + (uint32_t)grp * (2 * XBUF_BYTES);

    // ================= persistent pair loop (groups independent) =================
    for (int p = blockIdx.x; p < NPAIRS; p += gridDim.x) {
        const int pedb = (2 * p + grp) * M_TILE;
        BAR_SYNC(barid);   // group's previous tile fully drained

        // ---- init: h0 -> X[grp][0], c0 -> regs (group-local) ----
        for (int i = tg; i < 32 * 64; i += 256) {
            int r = i >> 6, kp = (i & 63) * 2;
            float2 hv = *(const float2*)(h0 + (size_t)(pedb + r) * 128 + kp);
            *(uint32_t*)(S + OFF_X + grp * (2 * XBUF_BYTES) + swz_off(r, kp)) =
                packh2(hv.x, hv.y);
        }
        float c_arr[16];   // [mt][up8][e][row8]
#pragma unroll
        for (int mt = 0; mt < 2; mt++)
#pragma unroll
            for (int up8 = 0; up8 < 2; up8++)
#pragma unroll
                for (int row8 = 0; row8 < 2; row8++) {
                    int gp = pedb + mt * 16 + g4 + row8 * 8;
                    int U0 = ng * 16 + up8 * 8 + c2;
                    float2 cv = *(const float2*)(c0 + (size_t)gp * 128 + U0);
                    c_arr[mt * 8 + up8 * 4 + row8]     = cv.x;
                    c_arr[mt * 8 + up8 * 4 + 2 + row8] = cv.y;
                }
        BAR_SYNC(barid);

        int par = 0;
        // ================= 12 recurrent steps =================
        for (int st = 0; st < STEPS; st++) {
            const uint32_t abase = xgbase + (uint32_t)par * XBUF_BYTES + arowoff;
            const uint32_t xw    = (uint32_t)grp * (2 * XBUF_BYTES) +
                                   (uint32_t)(par ^ 1) * XBUF_BYTES;

            // ---- main GEMM: gates = h @ Whh^T, plus rel cols h @ whp^T ----
            float acc[2][8][4];
            float rac[2][4];
#pragma unroll
            for (int mt = 0; mt < 2; mt++) {
#pragma unroll
                for (int nt = 0; nt < 8; nt++)
#pragma unroll
                    for (int j = 0; j < 4; j++) acc[mt][nt][j] = 0.f;
#pragma unroll
                for (int j = 0; j < 4; j++) rac[mt][j] = 0.f;
            }

#pragma unroll
            for (int kk = 0; kk < KK_STEPS; kk++) {
                const uint32_t koff = (((uint32_t)(2 * kk) + asel) ^ ax_) << 4;
                uint32_t a0[4], a1[4];
                LDSM_X4(a0[0], a0[1], a0[2], a0[3], abase + koff);
                LDSM_X4(a1[0], a1[1], a1[2], a1[3], abase + 4096 + koff);
                const uint32_t bkoff = (((uint32_t)(2 * kk) + bk_) ^ ax_) << 4;
#pragma unroll
                for (int t2 = 0; t2 < 4; t2++) {
                    uint32_t b0, b1, b2, b3;
                    LDSM_X4(b0, b1, b2, b3, bbase + (uint32_t)t2 * 4096 + bkoff);
                    MMA16816(acc[0][2 * t2],     a0[0], a0[1], a0[2], a0[3], b0, b1);
                    MMA16816(acc[0][2 * t2 + 1], a0[0], a0[1], a0[2], a0[3], b2, b3);
                    MMA16816(acc[1][2 * t2],     a1[0], a1[1], a1[2], a1[3], b0, b1);
                    MMA16816(acc[1][2 * t2 + 1], a1[0], a1[1], a1[2], a1[3], b2, b3);
                }
                {   // rel columns (n8): B rows 0..7 of WHPB
                    uint32_t p0, p1, p2, p3;
                    LDSM_X4(p0, p1, p2, p3, hpbase + bkoff);
                    MMA16816(rac[0], a0[0], a0[1], a0[2], a0[3], p0, p1);
                    MMA16816(rac[1], a1[0], a1[1], a1[2], a1[3], p0, p1);
                }
            }

            // ---- build X2 A fragment in registers; emit out[st-1] ----
            uint32_t xa0[2], xa1[2];
#pragma unroll
            for (int mt = 0; mt < 2; mt++) {
                if (is_c0) {
                    float rx0, ry0, rx1, ry1;
                    if (st == 0) {
                        int r0g = pedb + mt * 16 + g4;
                        float2 v0 = *(const float2*)(lpr + (size_t)r0g * 2);
                        float2 v1 = *(const float2*)(lpr + (size_t)(r0g + 8) * 2);
                        rx0 = v0.x; ry0 = v0.y; rx1 = v1.x; ry1 = v1.y;
                    } else {
                        rx0 = rac[mt][0] + bhx; ry0 = rac[mt][1] + bhy;
                        rx1 = rac[mt][2] + bhx; ry1 = rac[mt][3] + bhy;
                        if (ng == 0) {   // emit out[st-1]
                            int r0g = pedb + mt * 16 + g4;
                            out[(size_t)(st - 1) * 65536 + r0g]     = make_float2(rx0, ry0);
                            out[(size_t)(st - 1) * 65536 + r0g + 8] = make_float2(rx1, ry1);
                        }
                    }
                    xa0[mt] = packh2(rx0, ry0);
                    xa1[mt] = packh2(rx1, ry1);
                } else if (c2 == 2) {
                    xa0[mt] = C_ONE0; xa1[mt] = C_ONE0;
                } else {
                    xa0[mt] = 0u; xa1[mt] = 0u;
                }
            }

            {   // extra k16 step: rank-2 dec_in + bias ([rx,ry,1] @ W2^T)
#pragma unroll
                for (int t2 = 0; t2 < 4; t2++) {
                    uint32_t b0, b1, b2, b3;
                    LDSM_X4(b0, b1, b2, b3, w2base + (uint32_t)t2 * 768);
                    MMA16816(acc[0][2 * t2],     xa0[0], xa1[0], 0u, 0u, b0, b1);
                    MMA16816(acc[0][2 * t2 + 1], xa0[0], xa1[0], 0u, 0u, b2, b3);
                    MMA16816(acc[1][2 * t2],     xa0[1], xa1[1], 0u, 0u, b0, b1);
                    MMA16816(acc[1][2 * t2 + 1], xa0[1], xa1[1], 0u, 0u, b2, b3);
                }
            }

            // ---- epilogue: pure activations; new h -> other X buf ----
#pragma unroll
            for (int mt = 0; mt < 2; mt++) {
#pragma unroll
                for (int up8 = 0; up8 < 2; up8++) {
                    float hp[2][2];   // [row8][e]
#pragma unroll
                    for (int e = 0; e < 2; e++) {
#pragma unroll
                        for (int row8 = 0; row8 < 2; row8++) {
                            int reg = row8 * 2 + e;
                            float gi = acc[mt][up8][reg];
                            float gf = acc[mt][2 + up8][reg];
                            float gg = acc[mt][4 + up8][reg];
                            float go = acc[mt][6 + up8][reg];
                            int ci = mt * 8 + up8 * 4 + e * 2 + row8;
                            float cc = siga(gf) * c_arr[ci] + siga(gi) * tanh_ap(gg);
                            c_arr[ci] = cc;
                            float h = siga(go) * tanh_ap(cc);
                            hp[row8][e] = h;
                        }
                    }
                    int k0 = ng * 16 + up8 * 8 + c2;
#pragma unroll
                    for (int row8 = 0; row8 < 2; row8++) {
                        int r = mt * 16 + g4 + row8 * 8;
                        *(uint32_t*)(S + OFF_X + xw + swz_off(r, k0)) =
                            packh2(hp[row8][0], hp[row8][1]);
                    }
                }
            }
            BAR_SYNC(barid);   // group-local: X[grp][par^1] ready
            par ^= 1;
        }

        // ---- final rel pass: out[11] = h_12 @ whp^T + bhp (ng==0 warp) ----
        if (ng == 0) {
            const uint32_t abase = xgbase + (uint32_t)par * XBUF_BYTES + arowoff;
            float rac[2][4];
#pragma unroll
            for (int mt = 0; mt < 2; mt++)
#pragma unroll
                for (int j = 0; j < 4; j++) rac[mt][j] = 0.f;
#pragma unroll
            for (int kk = 0; kk < KK_STEPS; kk++) {
                const uint32_t koff = (((uint32_t)(2 * kk) + asel) ^ ax_) << 4;
                const uint32_t bkoff = (((uint32_t)(2 * kk) + bk_) ^ ax_) << 4;
                uint32_t a0[4], a1[4], p0, p1, p2, p3;
                LDSM_X4(a0[0], a0[1], a0[2], a0[3], abase + koff);
                LDSM_X4(a1[0], a1[1], a1[2], a1[3], abase + 4096 + koff);
                LDSM_X4(p0, p1, p2, p3, hpbase + bkoff);
                MMA16816(rac[0], a0[0], a0[1], a0[2], a0[3], p0, p1);
                MMA16816(rac[1], a1[0], a1[1], a1[2], a1[3], p0, p1);
            }
            if (is_c0) {
#pragma unroll
                for (int mt = 0; mt < 2; mt++) {
                    int r0g = pedb + mt * 16 + g4;
                    out[(size_t)11 * 65536 + r0g] =
                        make_float2(rac[mt][0] + bhx, rac[mt][1] + bhy);
                    out[(size_t)11 * 65536 + r0g + 8] =
                        make_float2(rac[mt][2] + bhx, rac[mt][3] + bhy);
                }
            }
        }
    }
}

extern "C" void kernel_launch(void* const* d_in, const int* in_sizes, int n_in,
                              void* d_out, int out_size) {
    (void)in_sizes; (void)n_in; (void)out_size;
    const float* lpr  = (const float*)d_in[1];
    const float* h0   = (const float*)d_in[2];
    const float* c0   = (const float*)d_in[3];
    const float* w_ih = (const float*)d_in[4];
    const float* w_hh = (const float*)d_in[5];
    const float* b_ih = (const float*)d_in[6];
    const float* b_hh = (const float*)d_in[7];
    const float* w_se = (const float*)d_in[8];
    const float* b_se = (const float*)d_in[9];
    const float* w_hp = (const float*)d_in[10];
    const float* b_hp = (const float*)d_in[11];

    cudaFuncSetAttribute(decoder_mma, cudaFuncAttributeMaxDynamicSharedMemorySize, SMEM_BYTES);
    decoder_mma<<<GRID, THREADS, SMEM_BYTES>>>(lpr, h0, c0, w_ih, w_hh, b_ih, b_hh,
                                               w_se, b_se, w_hp, b_hp, (float2*)d_out);
}

// round 13
// speedup vs baseline: 1.1104x; 1.0607x over previous
#include <cuda_runtime.h>
#include <cuda_fp16.h>
#include <cstdint>
#include <cstddef>

#define THREADS 512
#define NPAIRS  1024          // 65536 / 64 peds per pair-of-groups
#define GRID    148
#define STEPS   12
#define KD      128
#define KK_STEPS 8

// ---- smem layout (bytes from dynamic base) ----
#define OFF_W    0            // 512 rows * 256B fp16 swizzled     = 131072
#define OFF_W2   131072       // 512 rows * 48B  [wx,wy,bz,0..]    =  24576
#define OFF_X2   155648       // 2 grp x 32 rows * 48B             =   3072
#define OFF_X    158720       // 2 grp x 2 buf x (32*256B)         =  32768
#define XBUF_BYTES 8192
#define OFF_WHP  191488       // float[256]                        =   1024
#define OFF_PART 192512       // 2 grp x float[32][18]             =   4608
#define OFF_BHP  197120       // float[2]                          =      8
#define SMEM_BYTES 197248

__device__ __forceinline__ uint32_t smem_u32(const void* p) {
    uint32_t a;
    asm("{ .reg .u64 t; cvta.to.shared.u64 t, %1; cvt.u32.u64 %0, t; }" : "=r"(a) : "l"(p));
    return a;
}
__device__ __forceinline__ uint32_t packh2(float lo, float hi) {
    uint32_t r; asm("cvt.rn.f16x2.f32 %0, %1, %2;" : "=r"(r) : "f"(hi), "f"(lo)); return r;
}
__device__ __forceinline__ float tanh_ap(float x) {
    float y; asm("tanh.approx.f32 %0, %1;" : "=f"(y) : "f"(x)); return y;
}
__device__ __forceinline__ float siga(float x) { return fmaf(tanh_ap(0.5f * x), 0.5f, 0.5f); }

#define BAR_SYNC(id) asm volatile("bar.sync %0, 256;" :: "r"(id) : "memory")

#define LDSM_X4(r0, r1, r2, r3, addr)                                                  \
    asm volatile("ldmatrix.sync.aligned.m8n8.x4.shared.b16 {%0,%1,%2,%3}, [%4];"       \
                 : "=r"(r0), "=r"(r1), "=r"(r2), "=r"(r3) : "r"(addr))

#define MMA16816(d, a0, a1, a2, a3, b0, b1)                                            \
    asm volatile("mma.sync.aligned.m16n8k16.row.col.f32.f16.f16.f32 "                  \
                 "{%0,%1,%2,%3}, {%4,%5,%6,%7}, {%8,%9}, {%0,%1,%2,%3};"               \
                 : "+f"((d)[0]), "+f"((d)[1]), "+f"((d)[2]), "+f"((d)[3])              \
                 : "r"(a0), "r"(a1), "r"(a2), "r"(a3), "r"(b0), "r"(b1))

// swizzled byte offset within a 256B-row fp16 tile
__device__ __forceinline__ uint32_t swz_off(int r, int k) {
    return (uint32_t)(r * 256 + ((((k >> 3) ^ (r & 7)) << 4) | ((k & 7) * 2)));
}

__global__ __launch_bounds__(THREADS, 1)
void decoder_mma(const float* __restrict__ lpr, const float* __restrict__ h0,
                 const float* __restrict__ c0,
                 const float* __restrict__ w_ih, const float* __restrict__ w_hh,
                 const float* __restrict__ b_ih, const float* __restrict__ b_hh,
                 const float* __restrict__ w_se, const float* __restrict__ b_se,
                 const float* __restrict__ w_hp, const float* __restrict__ b_hp,
                 float2* __restrict__ out)
{
    extern __shared__ char S[];
    const uint32_t Sb = smem_u32(S);
    float* whp = (float*)(S + OFF_WHP);
    float* bhp = (float*)(S + OFF_BHP);

    const int tid = threadIdx.x, lane = tid & 31, w = tid >> 5;
    const int grp = w >> 3;                   // two independent 8-warp groups
    const int ng  = w & 7;                    // warp tile m32 x n64 within group
    const int tg  = tid & 255;
    const int g4 = lane >> 2, c2 = (lane & 3) * 2;
    const int barid = grp + 1;
    float* partg = (float*)(S + OFF_PART) + grp * 32 * 18;

    // ================= one-time prep (full CTA) =================
    for (int i = tid; i < 512 * KD; i += THREADS) {
        int n = i >> 7, k = i & 127;
        int grow = ((n >> 4) & 3) * 128 + (n >> 6) * 16 + (n & 15);
        *(__half*)(S + OFF_W + swz_off(n, k)) = __float2half_rn(w_hh[grow * 128 + k]);
    }
    for (int i = tid; i < (24576 + 3072) / 4; i += THREADS)   // zero W2 + X2
        ((uint32_t*)(S + OFF_W2))[i] = 0;
    if (tid < 256) whp[tid] = w_hp[tid];
    if (tid < 2)   bhp[tid] = b_hp[tid];
    __syncthreads();
    for (int n = tid; n < 512; n += THREADS) {   // rank-2 folded dec_in weights + bias
        int grow = ((n >> 4) & 3) * 128 + (n >> 6) * 16 + (n & 15);
        float wx = 0.f, wy = 0.f, bz = b_ih[grow] + b_hh[grow];
        for (int e = 0; e < 64; e++) {
            float wv = w_ih[grow * 64 + e];
            wx = fmaf(wv, w_se[e * 2],     wx);
            wy = fmaf(wv, w_se[e * 2 + 1], wy);
            bz = fmaf(wv, b_se[e],         bz);
        }
        __half* w2r = (__half*)(S + OFF_W2 + n * 48);
        w2r[0] = __float2half_rn(wx);
        w2r[1] = __float2half_rn(wy);
        w2r[2] = __float2half_rn(bz);
    }
    if (tid < 64)   // X2 col 2 = constant 1.0 (both groups, 32 rows each)
        ((__half*)(S + OFF_X2 + tid * 48))[2] = __float2half_rn(1.0f);
    __syncthreads();   // weights + X2 constants ready for both groups

    // ldmatrix per-lane address components
    const uint32_t ax_     = (uint32_t)(lane & 7);
    const uint32_t asel    = (uint32_t)(lane >> 4);
    const uint32_t arowoff = (uint32_t)(lane & 15) * 256;
    const uint32_t bdn     = (uint32_t)((lane & 7) + ((lane >> 4) << 3));
    const uint32_t bbase   = Sb + OFF_W + (uint32_t)(ng * 64 + bdn) * 256;
    const uint32_t bk_     = (uint32_t)((lane >> 3) & 1);
    const uint32_t w2base  = Sb + OFF_W2 + (uint32_t)(ng * 64 + bdn) * 48 + (bk_ << 4);
    const uint32_t x2base  = Sb + OFF_X2 + (uint32_t)grp * 1536 +
                             (uint32_t)(lane & 15) * 48 + (asel << 4);
    const uint32_t xgbase  = Sb + OFF_X + (uint32_t)grp * (2 * XBUF_BYTES);

    // ================= persistent pair loop (groups independent) =================
    for (int p = blockIdx.x; p < NPAIRS; p += gridDim.x) {
        const int pedb = (2 * p + grp) * 32;
        BAR_SYNC(barid);   // group's previous tile fully drained

        // ---- init: h0 -> X[grp][0], lpr -> X2[grp], c0 -> regs ----
        for (int i = tg; i < 32 * 64; i += 256) {
            int r = i >> 6, kp = (i & 63) * 2;
            float2 hv = *(const float2*)(h0 + (size_t)(pedb + r) * 128 + kp);
            *(uint32_t*)(S + OFF_X + grp * (2 * XBUF_BYTES) + swz_off(r, kp)) =
                packh2(hv.x, hv.y);
        }
        if (tg < 32) {
            float2 lv = *(const float2*)(lpr + (size_t)(pedb + tg) * 2);
            *(uint32_t*)(S + OFF_X2 + grp * 1536 + tg * 48) = packh2(lv.x, lv.y);
        }
        float c_arr[16];   // [mt][up8][e][row8]
#pragma unroll
        for (int mt = 0; mt < 2; mt++)
#pragma unroll
            for (int up8 = 0; up8 < 2; up8++)
#pragma unroll
                for (int row8 = 0; row8 < 2; row8++) {
                    int gp = pedb + mt * 16 + g4 + row8 * 8;
                    int U0 = ng * 16 + up8 * 8 + c2;
                    float2 cv = *(const float2*)(c0 + (size_t)gp * 128 + U0);
                    c_arr[mt * 8 + up8 * 4 + row8]     = cv.x;
                    c_arr[mt * 8 + up8 * 4 + 2 + row8] = cv.y;
                }
        BAR_SYNC(barid);

        int par = 0;
        // ================= 12 recurrent steps =================
        for (int st = 0; st < STEPS; st++) {
            const uint32_t abase = xgbase + (uint32_t)par * XBUF_BYTES + arowoff;
            const uint32_t xw    = (uint32_t)grp * (2 * XBUF_BYTES) +
                                   (uint32_t)(par ^ 1) * XBUF_BYTES;

            // ---- GEMM: gates = [h | rx,ry,1] @ [Whh | wx,wy,bz]^T ----
            float acc[2][8][4];
#pragma unroll
            for (int mt = 0; mt < 2; mt++)
#pragma unroll
                for (int nt = 0; nt < 8; nt++)
#pragma unroll
                    for (int j = 0; j < 4; j++) acc[mt][nt][j] = 0.f;

#pragma unroll
            for (int kk = 0; kk < KK_STEPS; kk++) {
                const uint32_t koff = (((uint32_t)(2 * kk) + asel) ^ ax_) << 4;
                uint32_t a0[4], a1[4];
                LDSM_X4(a0[0], a0[1], a0[2], a0[3], abase + koff);
                LDSM_X4(a1[0], a1[1], a1[2], a1[3], abase + 4096 + koff);
                const uint32_t bkoff = (((uint32_t)(2 * kk) + bk_) ^ ax_) << 4;
#pragma unroll
                for (int t2 = 0; t2 < 4; t2++) {
                    uint32_t b0, b1, b2, b3;
                    LDSM_X4(b0, b1, b2, b3, bbase + (uint32_t)t2 * 4096 + bkoff);
                    MMA16816(acc[0][2 * t2],     a0[0], a0[1], a0[2], a0[3], b0, b1);
                    MMA16816(acc[0][2 * t2 + 1], a0[0], a0[1], a0[2], a0[3], b2, b3);
                    MMA16816(acc[1][2 * t2],     a1[0], a1[1], a1[2], a1[3], b0, b1);
                    MMA16816(acc[1][2 * t2 + 1], a1[0], a1[1], a1[2], a1[3], b2, b3);
                }
            }
            {   // extra k16 step: rank-2 dec_in + bias (X2 @ W2^T)
                uint32_t a0[4], a1[4];
                LDSM_X4(a0[0], a0[1], a0[2], a0[3], x2base);
                LDSM_X4(a1[0], a1[1], a1[2], a1[3], x2base + 768);   // rows 16-31
#pragma unroll
                for (int t2 = 0; t2 < 4; t2++) {
                    uint32_t b0, b1, b2, b3;
                    LDSM_X4(b0, b1, b2, b3, w2base + (uint32_t)t2 * 768);
                    MMA16816(acc[0][2 * t2],     a0[0], a0[1], a0[2], a0[3], b0, b1);
                    MMA16816(acc[0][2 * t2 + 1], a0[0], a0[1], a0[2], a0[3], b2, b3);
                    MMA16816(acc[1][2 * t2],     a1[0], a1[1], a1[2], a1[3], b0, b1);
                    MMA16816(acc[1][2 * t2 + 1], a1[0], a1[1], a1[2], a1[3], b2, b3);
                }
            }

            // ---- epilogue: activations, h -> other X buf, rel partials ----
            float axs[2][2], ays[2][2];
#pragma unroll
            for (int mt = 0; mt < 2; mt++) {
                axs[mt][0] = ays[mt][0] = axs[mt][1] = ays[mt][1] = 0.f;
#pragma unroll
                for (int up8 = 0; up8 < 2; up8++) {
                    float hp[2][2];   // [row8][e]
#pragma unroll
                    for (int e = 0; e < 2; e++) {
                        int ul = up8 * 8 + c2 + e;
                        float wx_ = whp[ng * 16 + ul], wy_ = whp[128 + ng * 16 + ul];
#pragma unroll
                        for (int row8 = 0; row8 < 2; row8++) {
                            int reg = row8 * 2 + e;
                            float gi = acc[mt][up8][reg];
                            float gf = acc[mt][2 + up8][reg];
                            float gg = acc[mt][4 + up8][reg];
                            float go = acc[mt][6 + up8][reg];
                            int ci = mt * 8 + up8 * 4 + e * 2 + row8;
                            float cc = siga(gf) * c_arr[ci] + siga(gi) * tanh_ap(gg);
                            c_arr[ci] = cc;
                            float h = siga(go) * tanh_ap(cc);
                            axs[mt][row8] = fmaf(h, wx_, axs[mt][row8]);
                            ays[mt][row8] = fmaf(h, wy_, ays[mt][row8]);
                            hp[row8][e] = h;
                        }
                    }
                    int k0 = ng * 16 + up8 * 8 + c2;
#pragma unroll
                    for (int row8 = 0; row8 < 2; row8++) {
                        int r = mt * 16 + g4 + row8 * 8;
                        *(uint32_t*)(S + OFF_X + xw + swz_off(r, k0)) =
                            packh2(hp[row8][0], hp[row8][1]);
                    }
                }
            }
            // butterfly over the quad lanes (same peds, different units)
#pragma unroll
            for (int mt = 0; mt < 2; mt++)
#pragma unroll
                for (int row8 = 0; row8 < 2; row8++) {
                    float& ax = axs[mt][row8];
                    float& ay = ays[mt][row8];
                    ax += __shfl_xor_sync(~0u, ax, 1); ax += __shfl_xor_sync(~0u, ax, 2);
                    ay += __shfl_xor_sync(~0u, ay, 1); ay += __shfl_xor_sync(~0u, ay, 2);
                }
            if ((lane & 3) == 0) {
#pragma unroll
                for (int mt = 0; mt < 2; mt++)
#pragma unroll
                    for (int row8 = 0; row8 < 2; row8++) {
                        int r = mt * 16 + g4 + row8 * 8;
                        *(float2*)(partg + r * 18 + ng * 2) =
                            make_float2(axs[mt][row8], ays[mt][row8]);
                    }
            }
            BAR_SYNC(barid);   // group-local: X + part complete

            // ---- group reduce: rel = sum over 8 N-groups + b_hp; out; X2 ----
            if (tg < 32) {
                const float* pr = partg + tg * 18;
                float rx = pr[0] + pr[2] + pr[4] + pr[6] + pr[8] + pr[10] + pr[12] + pr[14] + bhp[0];
                float ry = pr[1] + pr[3] + pr[5] + pr[7] + pr[9] + pr[11] + pr[13] + pr[15] + bhp[1];
                out[(size_t)st * 65536 + pedb + tg] = make_float2(rx, ry);
                *(uint32_t*)(S + OFF_X2 + grp * 1536 + tg * 48) = packh2(rx, ry);
            }
            BAR_SYNC(barid);   // X2 ready for next step
            par ^= 1;
        }
    }
}

extern "C" void kernel_launch(void* const* d_in, const int* in_sizes, int n_in,
                              void* d_out, int out_size) {
    (void)in_sizes; (void)n_in; (void)out_size;
    const float* lpr  = (const float*)d_in[1];
    const float* h0   = (const float*)d_in[2];
    const float* c0   = (const float*)d_in[3];
    const float* w_ih = (const float*)d_in[4];
    const float* w_hh = (const float*)d_in[5];
    const float* b_ih = (const float*)d_in[6];
    const float* b_hh = (const float*)d_in[7];
    const float* w_se = (const float*)d_in[8];
    const float* b_se = (const float*)d_in[9];
    const float* w_hp = (const float*)d_in[10];
    const float* b_hp = (const float*)d_in[11];

    cudaFuncSetAttribute(decoder_mma, cudaFuncAttributeMaxDynamicSharedMemorySize, SMEM_BYTES);
    decoder_mma<<<GRID, THREADS, SMEM_BYTES>>>(lpr, h0, c0, w_ih, w_hh, b_ih, b_hh,
                                               w_se, b_se, w_hp, b_hp, (float2*)d_out);
}